// round 1
// baseline (speedup 1.0000x reference)
#include <cuda_runtime.h>

#define NT 256

// -------- persistent device scratch (no allocs allowed) --------
__device__ float g_h[65536 * 64];   // h = block2 output, needed for skip-concat
__device__ int   g_gmax[1024];      // global max-pool accumulator (float bits, >=0)
__device__ float g_c5[512];         // c5 = b5 + W5[:,64:] @ g

__device__ __forceinline__ float frelu(float v) { return v > 0.f ? v : 0.f; }

// Stage a [KS x CW] k-major weight slab into smem. W is row-major [out][ldW].
// Wb layout: Wb[k*(CW+4) + c]. Global reads are coalesced along k.
template <int KS, int CW>
__device__ __forceinline__ void stageW(float* __restrict__ Wb,
                                       const float* __restrict__ W,
                                       int ldW, int cbase, int kbase) {
    constexpr int SWB = CW + 4;
    for (int idx = threadIdx.x; idx < CW * KS; idx += NT) {
        int c = idx / KS;
        int k = idx - c * KS;
        Wb[k * SWB + c] = W[(cbase + c) * ldW + (kbase + k)];
    }
}

// Register-tiled GEMM slab: each thread accumulates TP points x 8 channels.
// A: smem activations [p][k] with row stride SA. Wb: smem k-major weights.
template <int TP, int PGR, int CW, int KS>
__device__ __forceinline__ void mma_slab(const float* __restrict__ A, int SA,
                                         const float* __restrict__ Wb,
                                         int pgrp, int cgrp, float acc[TP][8]) {
    constexpr int SWB = CW + 4;
    const float* Ap[TP];
#pragma unroll
    for (int i = 0; i < TP; i++) Ap[i] = A + (pgrp + i * PGR) * SA;
    const float* wp = Wb + cgrp * 8;
#pragma unroll 8
    for (int k = 0; k < KS; k++) {
        float4 w0 = *reinterpret_cast<const float4*>(wp + k * SWB);
        float4 w1 = *reinterpret_cast<const float4*>(wp + k * SWB + 4);
#pragma unroll
        for (int i = 0; i < TP; i++) {
            float a = Ap[i][k];
            acc[i][0] = fmaf(a, w0.x, acc[i][0]);
            acc[i][1] = fmaf(a, w0.y, acc[i][1]);
            acc[i][2] = fmaf(a, w0.z, acc[i][2]);
            acc[i][3] = fmaf(a, w0.w, acc[i][3]);
            acc[i][4] = fmaf(a, w1.x, acc[i][4]);
            acc[i][5] = fmaf(a, w1.y, acc[i][5]);
            acc[i][6] = fmaf(a, w1.z, acc[i][6]);
            acc[i][7] = fmaf(a, w1.w, acc[i][7]);
        }
    }
}

// -------- init: reset max-pool accumulator each replay --------
__global__ void k_init() {
    g_gmax[threadIdx.x] = 0;  // relu outputs >= 0, so float bits 0 is identity
}

// ============================================================
// Kernel A: blocks 1..4 fused + per-CTA max + global atomicMax.
// CTA = 128 points, 256 threads.
// smem floats: a3[128*132] hbuf[128*68] Wb[128*68] gmax[1024] consts[1856]
// ============================================================
#define SMEM1_FLOATS (128 * 132 + 128 * 68 + 128 * 68 + 1024 + 1856)

__global__ __launch_bounds__(NT, 1) void k_front(
    const float* __restrict__ x,
    const float* __restrict__ W1, const float* __restrict__ b1,
    const float* __restrict__ W2, const float* __restrict__ b2,
    const float* __restrict__ W3, const float* __restrict__ b3,
    const float* __restrict__ W4, const float* __restrict__ b4) {
    extern __shared__ float sm[];
    float* a3   = sm;                      // [128][132]  (a1 first, then a3)
    float* hbuf = a3 + 128 * 132;          // [128][68]
    float* Wb   = hbuf + 128 * 68;         // [128][68]
    int*   gmax = (int*)(Wb + 128 * 68);   // [1024]
    float* cst  = (float*)(gmax + 1024);
    float* w1s = cst;          // 192
    float* b1s = cst + 192;    // 64
    float* xs  = cst + 256;    // 384
    float* b2s = cst + 640;    // 64
    float* b3s = cst + 704;    // 128
    float* b4s = cst + 832;    // 1024

    const int tid   = threadIdx.x;
    const int pbase = blockIdx.x * 128;

    for (int i = tid; i < 1024; i += NT) gmax[i] = 0;
    for (int i = tid; i < 192; i += NT) w1s[i] = W1[i];
    for (int i = tid; i < 64; i += NT) { b1s[i] = b1[i]; b2s[i] = b2[i]; }
    for (int i = tid; i < 128; i += NT) b3s[i] = b3[i];
    for (int i = tid; i < 1024; i += NT) b4s[i] = b4[i];
    for (int i = tid; i < 384; i += NT) xs[i] = x[pbase * 3 + i];
    __syncthreads();

    // ---- block1: a1 = relu(x @ W1^T + b1) -> a3[:, :64]
    for (int idx = tid; idx < 128 * 64; idx += NT) {
        int p = idx >> 6, c = idx & 63;
        float v = fmaf(xs[p * 3 + 2], w1s[c * 3 + 2],
                  fmaf(xs[p * 3 + 1], w1s[c * 3 + 1],
                  fmaf(xs[p * 3 + 0], w1s[c * 3 + 0], b1s[c])));
        a3[p * 132 + c] = frelu(v);
    }
    __syncthreads();

    const int pgrp = tid >> 3;  // 0..31
    const int cgrp = tid & 7;   // 0..7

    // ---- block2: h = relu(a1 @ W2^T + b2) -> hbuf
    stageW<64, 64>(Wb, W2, 64, 0, 0);
    __syncthreads();
    {
        float acc[4][8];
#pragma unroll
        for (int i = 0; i < 4; i++)
#pragma unroll
            for (int j = 0; j < 8; j++) acc[i][j] = b2s[cgrp * 8 + j];
        mma_slab<4, 32, 64, 64>(a3, 132, Wb, pgrp, cgrp, acc);
#pragma unroll
        for (int i = 0; i < 4; i++)
#pragma unroll
            for (int j = 0; j < 8; j++)
                hbuf[(pgrp + i * 32) * 68 + cgrp * 8 + j] = frelu(acc[i][j]);
    }
    __syncthreads();
    // write h to global (needed by the back half)
    for (int idx = tid; idx < 128 * 64; idx += NT) {
        int p = idx >> 6, c = idx & 63;
        g_h[(pbase + p) * 64 + c] = hbuf[p * 68 + c];
    }

    // ---- block3: a3 = relu(h @ W3^T + b3), 128 ch in 2 chunks
    for (int cc = 0; cc < 2; cc++) {
        __syncthreads();
        stageW<64, 64>(Wb, W3, 64, cc * 64, 0);
        __syncthreads();
        float acc[4][8];
#pragma unroll
        for (int i = 0; i < 4; i++)
#pragma unroll
            for (int j = 0; j < 8; j++) acc[i][j] = b3s[cc * 64 + cgrp * 8 + j];
        mma_slab<4, 32, 64, 64>(hbuf, 68, Wb, pgrp, cgrp, acc);
#pragma unroll
        for (int i = 0; i < 4; i++)
#pragma unroll
            for (int j = 0; j < 8; j++)
                a3[(pgrp + i * 32) * 132 + cc * 64 + cgrp * 8 + j] = frelu(acc[i][j]);
    }

    // ---- block4: y4 = relu(a3 @ W4^T + b4), 1024 ch in 16 chunks; only max kept
    for (int cc = 0; cc < 16; cc++) {
        __syncthreads();
        stageW<128, 64>(Wb, W4, 128, cc * 64, 0);
        __syncthreads();
        float acc[4][8];
#pragma unroll
        for (int i = 0; i < 4; i++)
#pragma unroll
            for (int j = 0; j < 8; j++) acc[i][j] = b4s[cc * 64 + cgrp * 8 + j];
        mma_slab<4, 32, 64, 128>(a3, 132, Wb, pgrp, cgrp, acc);
#pragma unroll
        for (int j = 0; j < 8; j++) {
            float m = fmaxf(fmaxf(acc[0][j], acc[1][j]), fmaxf(acc[2][j], acc[3][j]));
            m = frelu(m);
            atomicMax(&gmax[cc * 64 + cgrp * 8 + j], __float_as_int(m));
        }
    }
    __syncthreads();
    for (int i = tid; i < 1024; i += NT) atomicMax(&g_gmax[i], gmax[i]);
}

// ============================================================
// Kernel B: c5[j] = b5[j] + sum_i W5[j][64+i] * g[i]
// grid 8 x 256 threads: 4 threads per j, deterministic shfl reduce.
// ============================================================
__global__ void k_c5(const float* __restrict__ W5, const float* __restrict__ b5) {
    __shared__ float gs[1024];
    const int tid = threadIdx.x;
    for (int i = tid; i < 1024; i += 256) gs[i] = __int_as_float(g_gmax[i]);
    __syncthreads();
    const int j = blockIdx.x * 64 + (tid >> 2);
    const int q = tid & 3;
    const float* wr = W5 + j * 1088 + 64 + q * 256;
    const float* gr = gs + q * 256;
    float s = 0.f;
#pragma unroll 8
    for (int i = 0; i < 256; i++) s = fmaf(wr[i], gr[i], s);
    s += __shfl_xor_sync(0xffffffffu, s, 1);
    s += __shfl_xor_sync(0xffffffffu, s, 2);
    if (q == 0) g_c5[j] = s + b5[j];
}

// ============================================================
// Kernel C: blocks 5..8 fused. CTA = 64 points, 256 threads.
// smem floats: z5[64*516] z6[64*260] Wb[32*132] consts[1056]
// (h overlays z6 region, z7 overlays z5 region)
// ============================================================
#define SMEM3_FLOATS (64 * 516 + 64 * 260 + 32 * 132 + 1056)

__global__ __launch_bounds__(NT, 1) void k_back(
    const float* __restrict__ W5,
    const float* __restrict__ W6, const float* __restrict__ b6,
    const float* __restrict__ W7, const float* __restrict__ b7,
    const float* __restrict__ W8, const float* __restrict__ b8,
    float* __restrict__ out) {
    extern __shared__ float sm[];
    float* z5  = sm;                    // [64][516]; z7 overlays as [64][132]
    float* z6  = z5 + 64 * 516;         // [64][260]; h overlays as [64][68]
    float* Wb  = z6 + 64 * 260;         // [32][132]
    float* cst = Wb + 32 * 132;
    float* c5s = cst;          // 512
    float* b6s = cst + 512;    // 256
    float* b7s = cst + 768;    // 128
    float* w8s = cst + 896;    // 128
    float* b8s = cst + 1024;   // 1
    float* hbuf = z6;          // stride 68

    const int tid   = threadIdx.x;
    const int pbase = blockIdx.x * 64;

    for (int i = tid; i < 512; i += NT) c5s[i] = g_c5[i];
    for (int i = tid; i < 256; i += NT) b6s[i] = b6[i];
    for (int i = tid; i < 128; i += NT) { b7s[i] = b7[i]; w8s[i] = W8[i]; }
    if (tid == 0) b8s[0] = b8[0];
    for (int idx = tid; idx < 64 * 64; idx += NT) {
        int p = idx >> 6, c = idx & 63;
        hbuf[p * 68 + c] = g_h[(pbase + p) * 64 + c];
    }

    const int pgrp = tid >> 4;  // 0..15
    const int cgrp = tid & 15;  // 0..15

    // ---- block5: z5 = relu(h @ W5a^T + c5), 512 ch in 4 chunks of 128, K=64
    for (int cc = 0; cc < 4; cc++) {
        float acc[4][8];
#pragma unroll
        for (int i = 0; i < 4; i++)
#pragma unroll
            for (int j = 0; j < 8; j++) acc[i][j] = c5s[cc * 128 + cgrp * 8 + j];
        for (int s = 0; s < 2; s++) {
            __syncthreads();
            stageW<32, 128>(Wb, W5, 1088, cc * 128, s * 32);
            __syncthreads();
            mma_slab<4, 16, 128, 32>(hbuf + s * 32, 68, Wb, pgrp, cgrp, acc);
        }
#pragma unroll
        for (int i = 0; i < 4; i++)
#pragma unroll
            for (int j = 0; j < 8; j++)
                z5[(pgrp + i * 16) * 516 + cc * 128 + cgrp * 8 + j] = frelu(acc[i][j]);
    }

    // ---- block6: z6 = relu(z5 @ W6^T + b6), 256 ch in 2 chunks, K=512
    for (int cc = 0; cc < 2; cc++) {
        float acc[4][8];
#pragma unroll
        for (int i = 0; i < 4; i++)
#pragma unroll
            for (int j = 0; j < 8; j++) acc[i][j] = b6s[cc * 128 + cgrp * 8 + j];
        for (int s = 0; s < 16; s++) {
            __syncthreads();
            stageW<32, 128>(Wb, W6, 512, cc * 128, s * 32);
            __syncthreads();
            mma_slab<4, 16, 128, 32>(z5 + s * 32, 516, Wb, pgrp, cgrp, acc);
        }
#pragma unroll
        for (int i = 0; i < 4; i++)
#pragma unroll
            for (int j = 0; j < 8; j++)
                z6[(pgrp + i * 16) * 260 + cc * 128 + cgrp * 8 + j] = frelu(acc[i][j]);
    }

    // ---- block7: z7 = relu(z6 @ W7^T + b7), 128 ch in 1 chunk, K=256
    {
        float acc[4][8];
#pragma unroll
        for (int i = 0; i < 4; i++)
#pragma unroll
            for (int j = 0; j < 8; j++) acc[i][j] = b7s[cgrp * 8 + j];
        for (int s = 0; s < 8; s++) {
            __syncthreads();
            stageW<32, 128>(Wb, W7, 256, 0, s * 32);
            __syncthreads();
            mma_slab<4, 16, 128, 32>(z6 + s * 32, 260, Wb, pgrp, cgrp, acc);
        }
        float* z7 = z5;  // overlay (z5 dead after block6)
#pragma unroll
        for (int i = 0; i < 4; i++)
#pragma unroll
            for (int j = 0; j < 8; j++)
                z7[(pgrp + i * 16) * 132 + cgrp * 8 + j] = frelu(acc[i][j]);
    }
    __syncthreads();

    // ---- block8: out = z7 @ W8^T + b8 (no relu)
    if (tid < 64) {
        const float* zr = z5 + tid * 132;
        float s = b8s[0];
#pragma unroll 8
        for (int k = 0; k < 128; k++) s = fmaf(zr[k], w8s[k], s);
        out[pbase + tid] = s;
    }
}

// ============================================================
extern "C" void kernel_launch(void* const* d_in, const int* in_sizes, int n_in,
                              void* d_out, int out_size) {
    const float* x  = (const float*)d_in[0];
    const float* W1 = (const float*)d_in[1];  const float* b1 = (const float*)d_in[2];
    const float* W2 = (const float*)d_in[3];  const float* b2 = (const float*)d_in[4];
    const float* W3 = (const float*)d_in[5];  const float* b3 = (const float*)d_in[6];
    const float* W4 = (const float*)d_in[7];  const float* b4 = (const float*)d_in[8];
    const float* W5 = (const float*)d_in[9];  const float* b5 = (const float*)d_in[10];
    const float* W6 = (const float*)d_in[11]; const float* b6 = (const float*)d_in[12];
    const float* W7 = (const float*)d_in[13]; const float* b7 = (const float*)d_in[14];
    const float* W8 = (const float*)d_in[15]; const float* b8 = (const float*)d_in[16];
    float* out = (float*)d_out;

    const int n = in_sizes[0] / 3;  // 65536

    const int smem1 = SMEM1_FLOATS * (int)sizeof(float);
    const int smem3 = SMEM3_FLOATS * (int)sizeof(float);
    cudaFuncSetAttribute(k_front, cudaFuncAttributeMaxDynamicSharedMemorySize, smem1);
    cudaFuncSetAttribute(k_back,  cudaFuncAttributeMaxDynamicSharedMemorySize, smem3);

    k_init<<<1, 1024>>>();
    k_front<<<n / 128, NT, smem1>>>(x, W1, b1, W2, b2, W3, b3, W4, b4);
    k_c5<<<8, 256>>>(W5, b5);
    k_back<<<n / 64, NT, smem3>>>(W5, W6, b6, W7, b7, W8, b8, out);
}

// round 2
// speedup vs baseline: 1.1141x; 1.1141x over previous
#include <cuda_runtime.h>

#define NT 256

typedef unsigned long long u64;

// -------- persistent device scratch (no allocs allowed) --------
__device__ float g_h[65536 * 64];   // h = block2 output, needed for skip-concat
__device__ int   g_gmax[1024];      // global max-pool accumulator (float bits, >=0)
__device__ float g_c5[512];         // c5 = b5 + W5[:,64:] @ g

__device__ __forceinline__ float frelu(float v) { return v > 0.f ? v : 0.f; }

// ---- packed f32x2 helpers (FFMA2: 2x fp32 throughput on sm_103a) ----
__device__ __forceinline__ u64 fma2(u64 a, u64 b, u64 c) {
    u64 d; asm("fma.rn.f32x2 %0, %1, %2, %3;" : "=l"(d) : "l"(a), "l"(b), "l"(c)); return d;
}
__device__ __forceinline__ u64 splat2(float a) {
    u64 d; asm("mov.b64 %0, {%1, %1};" : "=l"(d) : "f"(a)); return d;
}
__device__ __forceinline__ u64 pack2(float lo, float hi) {
    u64 d; asm("mov.b64 %0, {%1, %2};" : "=l"(d) : "f"(lo), "f"(hi)); return d;
}
__device__ __forceinline__ float2 unpack2(u64 v) {
    float2 f; asm("mov.b64 {%0, %1}, %2;" : "=f"(f.x), "=f"(f.y) : "l"(v)); return f;
}

// ---- weight slab staging with register prefetch (16 floats/thread) ----
// Slab = [KS x CW] k-major in smem: Wb[k*(CW+4) + c]. KS*CW must equal 16*NT.
template <int KS, int CW>
__device__ __forceinline__ void ldgW16(float r[16], const float* __restrict__ W,
                                       int ldW, int cbase, int kbase) {
    static_assert(KS * CW == 16 * NT, "slab size");
#pragma unroll
    for (int j = 0; j < 16; j++) {
        int idx = threadIdx.x + j * NT;
        int c = idx / KS, k = idx % KS;
        r[j] = __ldg(W + (cbase + c) * ldW + (kbase + k));
    }
}
template <int KS, int CW>
__device__ __forceinline__ void stsW16(float* __restrict__ Wb, const float r[16]) {
#pragma unroll
    for (int j = 0; j < 16; j++) {
        int idx = threadIdx.x + j * NT;
        int c = idx / KS, k = idx % KS;
        Wb[k * (CW + 4) + c] = r[j];
    }
}

// ---- register-tiled GEMM slab with packed channel pairs ----
// Each thread: TP points x 8 channels (4 f32x2 accumulators per point).
// A: smem activations [p][k], row stride SA. Wb: smem k-major weights.
template <int TP, int PGR, int CW, int KS>
__device__ __forceinline__ void mma2(const float* __restrict__ A, int SA,
                                     const float* __restrict__ Wb,
                                     int pgrp, int cgrp, u64 acc[TP][4]) {
    constexpr int SWB = CW + 4;
    const float* Ap[TP];
#pragma unroll
    for (int i = 0; i < TP; i++) Ap[i] = A + (pgrp + i * PGR) * SA;
    const char* wbase = (const char*)(Wb + cgrp * 8);
#pragma unroll 8
    for (int k = 0; k < KS; k++) {
        ulonglong2 u0 = *(const ulonglong2*)(wbase + (size_t)k * (SWB * 4));
        ulonglong2 u1 = *(const ulonglong2*)(wbase + (size_t)k * (SWB * 4) + 16);
#pragma unroll
        for (int i = 0; i < TP; i++) {
            u64 a2 = splat2(Ap[i][k]);
            acc[i][0] = fma2(a2, u0.x, acc[i][0]);
            acc[i][1] = fma2(a2, u0.y, acc[i][1]);
            acc[i][2] = fma2(a2, u1.x, acc[i][2]);
            acc[i][3] = fma2(a2, u1.y, acc[i][3]);
        }
    }
}

// -------- init: reset max-pool accumulator each replay --------
__global__ void k_init() {
    g_gmax[threadIdx.x] = 0;  // relu outputs >= 0, so float bits 0 is identity
}

// ============================================================
// Kernel A: blocks 1..4 fused + per-CTA max + global atomicMax.
// CTA = 128 points, 256 threads.
// smem floats: a3[128*132] hbuf[128*68] Wb[64*68] gmax[1024] consts[1856]
// ============================================================
#define SMEM1_FLOATS (128 * 132 + 128 * 68 + 64 * 68 + 1024 + 1856)

__global__ __launch_bounds__(NT, 1) void k_front(
    const float* __restrict__ x,
    const float* __restrict__ W1, const float* __restrict__ b1,
    const float* __restrict__ W2, const float* __restrict__ b2,
    const float* __restrict__ W3, const float* __restrict__ b3,
    const float* __restrict__ W4, const float* __restrict__ b4) {
    extern __shared__ float sm[];
    float* a3   = sm;                      // [128][132]  (a1 first, then a3)
    float* hbuf = a3 + 128 * 132;          // [128][68]
    float* Wb   = hbuf + 128 * 68;         // [64][68]
    int*   gmax = (int*)(Wb + 64 * 68);    // [1024]
    float* cst  = (float*)(gmax + 1024);
    float* w1s = cst;          // 192
    float* b1s = cst + 192;    // 64
    float* xs  = cst + 256;    // 384
    float* b2s = cst + 640;    // 64
    float* b3s = cst + 704;    // 128
    float* b4s = cst + 832;    // 1024

    const int tid   = threadIdx.x;
    const int pbase = blockIdx.x * 128;

    for (int i = tid; i < 1024; i += NT) gmax[i] = 0;
    for (int i = tid; i < 192; i += NT) w1s[i] = W1[i];
    for (int i = tid; i < 64; i += NT) { b1s[i] = b1[i]; b2s[i] = b2[i]; }
    for (int i = tid; i < 128; i += NT) b3s[i] = b3[i];
    for (int i = tid; i < 1024; i += NT) b4s[i] = b4[i];
    for (int i = tid; i < 384; i += NT) xs[i] = x[pbase * 3 + i];

    float rw[16];
    ldgW16<64, 64>(rw, W2, 64, 0, 0);     // prefetch W2 slab
    __syncthreads();

    // ---- block1: a1 = relu(x @ W1^T + b1) -> a3[:, :64]
    for (int idx = tid; idx < 128 * 64; idx += NT) {
        int p = idx >> 6, c = idx & 63;
        float v = fmaf(xs[p * 3 + 2], w1s[c * 3 + 2],
                  fmaf(xs[p * 3 + 1], w1s[c * 3 + 1],
                  fmaf(xs[p * 3 + 0], w1s[c * 3 + 0], b1s[c])));
        a3[p * 132 + c] = frelu(v);
    }
    __syncthreads();

    stsW16<64, 64>(Wb, rw);
    ldgW16<64, 64>(rw, W3, 64, 0, 0);     // prefetch W3 chunk0
    __syncthreads();

    const int pgrp = tid >> 3;  // 0..31
    const int cgrp = tid & 7;   // 0..7
    const int c0   = cgrp * 8;

    // ---- block2: h = relu(a1 @ W2^T + b2) -> hbuf
    {
        u64 acc[4][4];
#pragma unroll
        for (int i = 0; i < 4; i++)
#pragma unroll
            for (int j = 0; j < 4; j++) acc[i][j] = pack2(b2s[c0 + 2 * j], b2s[c0 + 2 * j + 1]);
        mma2<4, 32, 64, 64>(a3, 132, Wb, pgrp, cgrp, acc);
#pragma unroll
        for (int i = 0; i < 4; i++)
#pragma unroll
            for (int j = 0; j < 4; j++) {
                float2 f = unpack2(acc[i][j]);
                hbuf[(pgrp + i * 32) * 68 + c0 + 2 * j]     = frelu(f.x);
                hbuf[(pgrp + i * 32) * 68 + c0 + 2 * j + 1] = frelu(f.y);
            }
    }
    __syncthreads();

    stsW16<64, 64>(Wb, rw);
    ldgW16<64, 64>(rw, W3, 64, 64, 0);    // prefetch W3 chunk1
    __syncthreads();

    // write h to global (needed by the back half)
    for (int idx = tid; idx < 128 * 64; idx += NT) {
        int p = idx >> 6, c = idx & 63;
        g_h[(pbase + p) * 64 + c] = hbuf[p * 68 + c];
    }

    // ---- block3 chunk 0: a3[:, :64]
    {
        u64 acc[4][4];
#pragma unroll
        for (int i = 0; i < 4; i++)
#pragma unroll
            for (int j = 0; j < 4; j++) acc[i][j] = pack2(b3s[c0 + 2 * j], b3s[c0 + 2 * j + 1]);
        mma2<4, 32, 64, 64>(hbuf, 68, Wb, pgrp, cgrp, acc);
#pragma unroll
        for (int i = 0; i < 4; i++)
#pragma unroll
            for (int j = 0; j < 4; j++) {
                float2 f = unpack2(acc[i][j]);
                a3[(pgrp + i * 32) * 132 + c0 + 2 * j]     = frelu(f.x);
                a3[(pgrp + i * 32) * 132 + c0 + 2 * j + 1] = frelu(f.y);
            }
    }
    __syncthreads();

    stsW16<64, 64>(Wb, rw);
    ldgW16<64, 64>(rw, W4, 128, 0, 0);    // prefetch W4 stage 0
    __syncthreads();

    // ---- block3 chunk 1: a3[:, 64:]
    {
        u64 acc[4][4];
#pragma unroll
        for (int i = 0; i < 4; i++)
#pragma unroll
            for (int j = 0; j < 4; j++) acc[i][j] = pack2(b3s[64 + c0 + 2 * j], b3s[64 + c0 + 2 * j + 1]);
        mma2<4, 32, 64, 64>(hbuf, 68, Wb, pgrp, cgrp, acc);
#pragma unroll
        for (int i = 0; i < 4; i++)
#pragma unroll
            for (int j = 0; j < 4; j++) {
                float2 f = unpack2(acc[i][j]);
                a3[(pgrp + i * 32) * 132 + 64 + c0 + 2 * j]     = frelu(f.x);
                a3[(pgrp + i * 32) * 132 + 64 + c0 + 2 * j + 1] = frelu(f.y);
            }
    }

    // ---- block4: 16 channel chunks x 2 k-substages (KS=64); only max kept
    for (int cc = 0; cc < 16; cc++) {
        u64 acc[4][4];
#pragma unroll
        for (int i = 0; i < 4; i++)
#pragma unroll
            for (int j = 0; j < 4; j++)
                acc[i][j] = pack2(b4s[cc * 64 + c0 + 2 * j], b4s[cc * 64 + c0 + 2 * j + 1]);
        for (int s = 0; s < 2; s++) {
            __syncthreads();
            stsW16<64, 64>(Wb, rw);
            int t = cc * 2 + s + 1;
            if (t < 32) ldgW16<64, 64>(rw, W4, 128, (t >> 1) * 64, (t & 1) * 64);
            __syncthreads();
            mma2<4, 32, 64, 64>(a3 + s * 64, 132, Wb, pgrp, cgrp, acc);
        }
#pragma unroll
        for (int j = 0; j < 4; j++) {
            float2 f0 = unpack2(acc[0][j]);
            float2 f1 = unpack2(acc[1][j]);
            float2 f2 = unpack2(acc[2][j]);
            float2 f3 = unpack2(acc[3][j]);
            float mx = frelu(fmaxf(fmaxf(f0.x, f1.x), fmaxf(f2.x, f3.x)));
            float my = frelu(fmaxf(fmaxf(f0.y, f1.y), fmaxf(f2.y, f3.y)));
            atomicMax(&gmax[cc * 64 + c0 + 2 * j],     __float_as_int(mx));
            atomicMax(&gmax[cc * 64 + c0 + 2 * j + 1], __float_as_int(my));
        }
    }
    __syncthreads();
    for (int i = tid; i < 1024; i += NT) atomicMax(&g_gmax[i], gmax[i]);
}

// ============================================================
// Kernel B: c5[j] = b5[j] + sum_i W5[j][64+i] * g[i]
// ============================================================
__global__ void k_c5(const float* __restrict__ W5, const float* __restrict__ b5) {
    __shared__ float gs[1024];
    const int tid = threadIdx.x;
    for (int i = tid; i < 1024; i += 256) gs[i] = __int_as_float(g_gmax[i]);
    __syncthreads();
    const int j = blockIdx.x * 64 + (tid >> 2);
    const int q = tid & 3;
    const float* wr = W5 + j * 1088 + 64 + q * 256;
    const float* gr = gs + q * 256;
    float s = 0.f;
#pragma unroll 8
    for (int i = 0; i < 256; i++) s = fmaf(wr[i], gr[i], s);
    s += __shfl_xor_sync(0xffffffffu, s, 1);
    s += __shfl_xor_sync(0xffffffffu, s, 2);
    if (q == 0) g_c5[j] = s + b5[j];
}

// ============================================================
// Kernel C: blocks 5..8 fused. CTA = 64 points, 256 threads.
// smem floats: z5[64*516] z6[64*260] Wb[32*132] consts[1056]
// (h overlays z6 region, z7 overlays z5 region)
// ============================================================
#define SMEM3_FLOATS (64 * 516 + 64 * 260 + 32 * 132 + 1056)

__global__ __launch_bounds__(NT, 1) void k_back(
    const float* __restrict__ W5,
    const float* __restrict__ W6, const float* __restrict__ b6,
    const float* __restrict__ W7, const float* __restrict__ b7,
    const float* __restrict__ W8, const float* __restrict__ b8,
    float* __restrict__ out) {
    extern __shared__ float sm[];
    float* z5  = sm;                    // [64][516]; z7 overlays as [64][132]
    float* z6  = z5 + 64 * 516;         // [64][260]; h overlays as [64][68]
    float* Wb  = z6 + 64 * 260;         // [32][132]
    float* cst = Wb + 32 * 132;
    float* c5s = cst;          // 512
    float* b6s = cst + 512;    // 256
    float* b7s = cst + 768;    // 128
    float* w8s = cst + 896;    // 128
    float* b8s = cst + 1024;   // 1
    float* hbuf = z6;          // stride 68 (h overlays z6 region during block5)

    const int tid   = threadIdx.x;
    const int pbase = blockIdx.x * 64;

    for (int i = tid; i < 512; i += NT) c5s[i] = g_c5[i];
    for (int i = tid; i < 256; i += NT) b6s[i] = b6[i];
    for (int i = tid; i < 128; i += NT) { b7s[i] = b7[i]; w8s[i] = W8[i]; }
    if (tid == 0) b8s[0] = b8[0];
    for (int idx = tid; idx < 64 * 64; idx += NT) {
        int p = idx >> 6, c = idx & 63;
        hbuf[p * 68 + c] = g_h[(pbase + p) * 64 + c];
    }

    float rw[16];
    ldgW16<32, 128>(rw, W5, 1088, 0, 0);   // prefetch W5 stage 0
    __syncthreads();

    const int pgrp = tid >> 4;  // 0..15
    const int cgrp = tid & 15;  // 0..15
    const int c0   = cgrp * 8;

    // ---- block5: z5 = relu(h @ W5a^T + c5), 4 chunks of 128 ch, K=64 (2 substages)
    for (int cc = 0; cc < 4; cc++) {
        u64 acc[4][4];
#pragma unroll
        for (int i = 0; i < 4; i++)
#pragma unroll
            for (int j = 0; j < 4; j++)
                acc[i][j] = pack2(c5s[cc * 128 + c0 + 2 * j], c5s[cc * 128 + c0 + 2 * j + 1]);
        for (int s = 0; s < 2; s++) {
            __syncthreads();
            stsW16<32, 128>(Wb, rw);
            int t = cc * 2 + s + 1;
            if (t < 8)       ldgW16<32, 128>(rw, W5, 1088, (t >> 1) * 128, (t & 1) * 32);
            else if (t == 8) ldgW16<32, 128>(rw, W6, 512, 0, 0);
            __syncthreads();
            mma2<4, 16, 128, 32>(hbuf + s * 32, 68, Wb, pgrp, cgrp, acc);
        }
#pragma unroll
        for (int i = 0; i < 4; i++)
#pragma unroll
            for (int j = 0; j < 4; j++) {
                float2 f = unpack2(acc[i][j]);
                z5[(pgrp + i * 16) * 516 + cc * 128 + c0 + 2 * j]     = frelu(f.x);
                z5[(pgrp + i * 16) * 516 + cc * 128 + c0 + 2 * j + 1] = frelu(f.y);
            }
    }

    // ---- block6: z6 = relu(z5 @ W6^T + b6), 2 chunks of 128 ch, K=512 (16 substages)
    for (int cc = 0; cc < 2; cc++) {
        u64 acc[4][4];
#pragma unroll
        for (int i = 0; i < 4; i++)
#pragma unroll
            for (int j = 0; j < 4; j++)
                acc[i][j] = pack2(b6s[cc * 128 + c0 + 2 * j], b6s[cc * 128 + c0 + 2 * j + 1]);
        for (int s = 0; s < 16; s++) {
            __syncthreads();
            stsW16<32, 128>(Wb, rw);
            int t = cc * 16 + s + 1;
            if (t < 32)       ldgW16<32, 128>(rw, W6, 512, (t >> 4) * 128, (t & 15) * 32);
            else if (t == 32) ldgW16<32, 128>(rw, W7, 256, 0, 0);
            __syncthreads();
            mma2<4, 16, 128, 32>(z5 + s * 32, 516, Wb, pgrp, cgrp, acc);
        }
#pragma unroll
        for (int i = 0; i < 4; i++)
#pragma unroll
            for (int j = 0; j < 4; j++) {
                float2 f = unpack2(acc[i][j]);
                z6[(pgrp + i * 16) * 260 + cc * 128 + c0 + 2 * j]     = frelu(f.x);
                z6[(pgrp + i * 16) * 260 + cc * 128 + c0 + 2 * j + 1] = frelu(f.y);
            }
    }

    // ---- block7: z7 = relu(z6 @ W7^T + b7), 128 ch, K=256 (8 substages)
    {
        u64 acc[4][4];
#pragma unroll
        for (int i = 0; i < 4; i++)
#pragma unroll
            for (int j = 0; j < 4; j++)
                acc[i][j] = pack2(b7s[c0 + 2 * j], b7s[c0 + 2 * j + 1]);
        for (int s = 0; s < 8; s++) {
            __syncthreads();
            stsW16<32, 128>(Wb, rw);
            if (s < 7) ldgW16<32, 128>(rw, W7, 256, 0, (s + 1) * 32);
            __syncthreads();
            mma2<4, 16, 128, 32>(z6 + s * 32, 260, Wb, pgrp, cgrp, acc);
        }
        float* z7 = z5;  // overlay (z5 dead after block6)
#pragma unroll
        for (int i = 0; i < 4; i++)
#pragma unroll
            for (int j = 0; j < 4; j++) {
                float2 f = unpack2(acc[i][j]);
                z7[(pgrp + i * 16) * 132 + c0 + 2 * j]     = frelu(f.x);
                z7[(pgrp + i * 16) * 132 + c0 + 2 * j + 1] = frelu(f.y);
            }
    }
    __syncthreads();

    // ---- block8: out = z7 @ W8^T + b8 (no relu)
    if (tid < 64) {
        const float* zr = z5 + tid * 132;
        float s = b8s[0];
#pragma unroll 8
        for (int k = 0; k < 128; k++) s = fmaf(zr[k], w8s[k], s);
        out[pbase + tid] = s;
    }
}

// ============================================================
extern "C" void kernel_launch(void* const* d_in, const int* in_sizes, int n_in,
                              void* d_out, int out_size) {
    const float* x  = (const float*)d_in[0];
    const float* W1 = (const float*)d_in[1];  const float* b1 = (const float*)d_in[2];
    const float* W2 = (const float*)d_in[3];  const float* b2 = (const float*)d_in[4];
    const float* W3 = (const float*)d_in[5];  const float* b3 = (const float*)d_in[6];
    const float* W4 = (const float*)d_in[7];  const float* b4 = (const float*)d_in[8];
    const float* W5 = (const float*)d_in[9];  const float* b5 = (const float*)d_in[10];
    const float* W6 = (const float*)d_in[11]; const float* b6 = (const float*)d_in[12];
    const float* W7 = (const float*)d_in[13]; const float* b7 = (const float*)d_in[14];
    const float* W8 = (const float*)d_in[15]; const float* b8 = (const float*)d_in[16];
    float* out = (float*)d_out;

    const int n = in_sizes[0] / 3;  // 65536

    const int smem1 = SMEM1_FLOATS * (int)sizeof(float);
    const int smem3 = SMEM3_FLOATS * (int)sizeof(float);
    cudaFuncSetAttribute(k_front, cudaFuncAttributeMaxDynamicSharedMemorySize, smem1);
    cudaFuncSetAttribute(k_back,  cudaFuncAttributeMaxDynamicSharedMemorySize, smem3);

    k_init<<<1, 1024>>>();
    k_front<<<n / 128, NT, smem1>>>(x, W1, b1, W2, b2, W3, b3, W4, b4);
    k_c5<<<8, 256>>>(W5, b5);
    k_back<<<n / 64, NT, smem3>>>(W5, W6, b6, W7, b7, W8, b8, out);
}